// round 7
// baseline (speedup 1.0000x reference)
#include <cuda_runtime.h>
#include <math.h>
#include <stdint.h>

// Problem dims (fixed)
#define Bz 16
#define Tt 4096
#define Hd 512
#define G3 1536            // 3*Hd

// Cluster scan config
#define CL 16              // CTAs per cluster (non-portable size)
#define NCL 8              // clusters (each owns 2 batch elements)
#define NBLK (CL*NCL)      // 128 CTAs
#define SCAN_THREADS 384   // 12 warps
#define JPC 32             // hidden units per CTA

// ---------------------------------------------------------------------------
// Scratch (device globals; no allocation allowed)
// ---------------------------------------------------------------------------
__device__ float g_xp[(size_t)Bz * Tt * G3];    // xp1, then reused for xp2
__device__ float g_a [(size_t)Bz * Tt * Hd];    // gelu(h1)

// ---------------------------------------------------------------------------
// Packed fp32x2 helpers (Blackwell FFMA2 via PTX)
// ---------------------------------------------------------------------------
__device__ __forceinline__ unsigned long long ffma2(unsigned long long a,
                                                    unsigned long long b,
                                                    unsigned long long c)
{
    unsigned long long d;
    asm("fma.rn.f32x2 %0, %1, %2, %3;" : "=l"(d) : "l"(a), "l"(b), "l"(c));
    return d;
}
__device__ __forceinline__ unsigned long long pack2(float lo, float hi)
{
    unsigned long long r;
    asm("mov.b64 %0, {%1, %2};" : "=l"(r) : "r"(__float_as_uint(lo)), "r"(__float_as_uint(hi)));
    return r;
}
__device__ __forceinline__ float f2lo(unsigned long long v) { return __uint_as_float((unsigned)v); }
__device__ __forceinline__ float f2hi(unsigned long long v) { return __uint_as_float((unsigned)(v >> 32)); }

__device__ __forceinline__ uint32_t smem_u32(const void* p)
{
    uint32_t a;
    asm("{ .reg .u64 t; cvta.to.shared.u64 t, %1; cvt.u32.u64 %0, t; }" : "=r"(a) : "l"(p));
    return a;
}
__device__ __forceinline__ void sts_cluster_f32(uint32_t laddr, int rank, float v)
{
    uint32_t r;
    asm volatile("mapa.shared::cluster.u32 %0, %1, %2;" : "=r"(r) : "r"(laddr), "r"(rank));
    asm volatile("st.shared::cluster.f32 [%0], %1;" :: "r"(r), "f"(v) : "memory");
}
__device__ __forceinline__ void mbar_init(uint32_t laddr, unsigned count)
{
    asm volatile("mbarrier.init.shared.b64 [%0], %1;" :: "r"(laddr), "r"(count) : "memory");
}
__device__ __forceinline__ void mbar_arrive_remote(uint32_t laddr, int rank)
{
    uint32_t r;
    asm volatile("mapa.shared::cluster.u32 %0, %1, %2;" : "=r"(r) : "r"(laddr), "r"(rank));
    asm volatile("mbarrier.arrive.release.cluster.shared::cluster.b64 _, [%0];" :: "r"(r) : "memory");
}
__device__ __forceinline__ void mbar_wait_parity(uint32_t laddr, uint32_t parity)
{
    asm volatile(
        "{\n\t"
        ".reg .pred P;\n\t"
        "WAITLP_%=:\n\t"
        "mbarrier.try_wait.parity.acquire.cluster.shared::cta.b64 P, [%0], %1, 0x989680;\n\t"
        "@!P bra WAITLP_%=;\n\t"
        "}"
        :: "r"(laddr), "r"(parity) : "memory");
}
__device__ __forceinline__ void fence_cluster() {
    asm volatile("fence.acq_rel.cluster;" ::: "memory");
}
__device__ __forceinline__ void cluster_arrive() {
    asm volatile("barrier.cluster.arrive.aligned;" ::: "memory");
}
__device__ __forceinline__ void cluster_wait() {
    asm volatile("barrier.cluster.wait.aligned;" ::: "memory");
}

__device__ __forceinline__ float sigmoidf_(float x) { return 1.0f / (1.0f + expf(-x)); }
__device__ __forceinline__ float gelu_erf(float x) {
    return 0.5f * x * (1.0f + erff(x * 0.70710678118654752f));
}

// ---------------------------------------------------------------------------
// GEMM: C[M][1536] = A[M][512] * W[1536][512]^T + bias[1536]
// 128x128 tile, 256 threads, 8x8 per thread via FFMA2.
// B pairs packed at use on the ALU pipe (no duplicated smem -> 16KB/k-iter).
// ---------------------------------------------------------------------------
__global__ __launch_bounds__(256, 2) void gemm_nt_bias(
    const float* __restrict__ A, const float* __restrict__ W,
    const float* __restrict__ bias, float* __restrict__ C)
{
    __shared__ float as[16][132];
    __shared__ float bs[16][132];

    const int m0 = blockIdx.y * 128;
    const int n0 = blockIdx.x * 128;
    const int tid = threadIdx.x;
    const int tx = tid & 15;        // n direction
    const int ty = tid >> 4;        // m direction

    unsigned long long acc[4][8];
#pragma unroll
    for (int i = 0; i < 4; i++)
#pragma unroll
        for (int j = 0; j < 8; j++) acc[i][j] = 0ull;

    for (int kc = 0; kc < 512; kc += 16) {
#pragma unroll
        for (int it = 0; it < 2; it++) {
            int f = tid + it * 256;          // 0..511
            int row = f >> 2;
            int kq = (f & 3) * 4;
            float4 va = *(const float4*)&A[(size_t)(m0 + row) * 512 + kc + kq];
            as[kq + 0][row] = va.x; as[kq + 1][row] = va.y;
            as[kq + 2][row] = va.z; as[kq + 3][row] = va.w;
            float4 vb = *(const float4*)&W[(size_t)(n0 + row) * 512 + kc + kq];
            bs[kq + 0][row] = vb.x; bs[kq + 1][row] = vb.y;
            bs[kq + 2][row] = vb.z; bs[kq + 3][row] = vb.w;
        }
        __syncthreads();

#pragma unroll
        for (int k = 0; k < 16; k++) {
            ulonglong2 aA = *(const ulonglong2*)&as[k][ty * 4];       // rows r0r1, r2r3
            ulonglong2 aB = *(const ulonglong2*)&as[k][64 + ty * 4];
            float4 b0 = *(const float4*)&bs[k][tx * 4];
            float4 b1 = *(const float4*)&bs[k][64 + tx * 4];
            unsigned long long ap[4] = { aA.x, aA.y, aB.x, aB.y };
            unsigned long long bd[8] = {
                pack2(b0.x, b0.x), pack2(b0.y, b0.y), pack2(b0.z, b0.z), pack2(b0.w, b0.w),
                pack2(b1.x, b1.x), pack2(b1.y, b1.y), pack2(b1.z, b1.z), pack2(b1.w, b1.w)
            };
#pragma unroll
            for (int ip = 0; ip < 4; ip++)
#pragma unroll
                for (int j = 0; j < 8; j++)
                    acc[ip][j] = ffma2(ap[ip], bd[j], acc[ip][j]);
        }
        __syncthreads();
    }

    // Epilogue. acc[ip][j]: lo = even row of pair, hi = odd row.
    float4 bv0 = *(const float4*)&bias[n0 + tx * 4];
    float4 bv1 = *(const float4*)&bias[n0 + 64 + tx * 4];
    const float bj[8] = { bv0.x, bv0.y, bv0.z, bv0.w, bv1.x, bv1.y, bv1.z, bv1.w };
#pragma unroll
    for (int ip = 0; ip < 4; ip++) {
#pragma unroll
        for (int half = 0; half < 2; half++) {
            int m = m0 + ((ip >> 1) ? 64 : 0) + ty * 4 + (ip & 1) * 2 + half;
            float o[8];
#pragma unroll
            for (int j = 0; j < 8; j++)
                o[j] = (half ? f2hi(acc[ip][j]) : f2lo(acc[ip][j])) + bj[j];
            *(float4*)&C[(size_t)m * G3 + n0 + tx * 4]      = make_float4(o[0], o[1], o[2], o[3]);
            *(float4*)&C[(size_t)m * G3 + n0 + 64 + tx * 4] = make_float4(o[4], o[5], o[6], o[7]);
        }
    }
}

// ---------------------------------------------------------------------------
// Cluster-based GRU scan, w_hh resident in REGISTERS.
// 8 clusters x 16 CTAs; cluster c owns batch {2c, 2c+1}; CTA rank r owns hidden
// units [32r, 32r+32). Thread (warp w, lane l): gate g = w>>2, k-split ks = w&3,
// holds w_hh[g*512 + j0 + l][ks*128 .. +128) in 64 ull registers.
// Per step: 64 broadcast LDS + 128 FFMA2 per thread; smem reduction over ks;
// 64 gate threads update h, broadcast via st.shared::cluster; tid0 fences and
// arrives on every rank's per-buffer mbarrier (16 arrivals/phase, auto-rearm);
// all threads acquire-wait. No barrier.cluster in the loop (no L1 flush).
// ---------------------------------------------------------------------------
__global__ __launch_bounds__(SCAN_THREADS, 1) void gru_scan_cl(
    const float* __restrict__ xp, const float* __restrict__ w_hh,
    const float* __restrict__ b_hh, float* __restrict__ out, int do_gelu)
{
    __shared__ float hs[2][2 * Hd];                    // [buf][b*512 + k]
    __shared__ float red[96 * 4 * 2];                  // [cc][ks][b]
    __shared__ __align__(8) unsigned long long mbar[2];

    const int tid = threadIdx.x;
    uint32_t rank;
    asm("mov.u32 %0, %%cluster_ctarank;" : "=r"(rank));
    const int cid = blockIdx.x >> 4;       // cluster id 0..7
    const int j0 = rank * JPC;

    const int warp = tid >> 5, lane = tid & 31;
    const int ks = warp & 3;
    const int g  = warp >> 2;              // gate 0..2
    const int k0 = ks * 128;

    // ---- Load this thread's w slice into registers (one-time) ----
    const float* wsrc = w_hh + (size_t)(g * Hd + j0 + lane) * Hd + k0;
    unsigned long long wreg[64];
#pragma unroll
    for (int i = 0; i < 32; i++) {
        float4 v = *(const float4*)(wsrc + i * 4);
        wreg[2 * i]     = pack2(v.x, v.y);
        wreg[2 * i + 1] = pack2(v.z, v.w);
    }

    // ---- Init smem state + mbarriers ----
    for (int i = tid; i < 2 * Hd; i += SCAN_THREADS) hs[0][i] = 0.f;
    const uint32_t hs_base = smem_u32(&hs[0][0]);
    const uint32_t mb_base = smem_u32(&mbar[0]);
    if (tid == 0) {
        mbar_init(mb_base,     CL);   // buffer 0 barrier: 16 arrivals/phase
        mbar_init(mb_base + 8, CL);   // buffer 1 barrier
    }
    __syncthreads();
    cluster_arrive();                 // mbarriers + zeroed h visible cluster-wide
    cluster_wait();

    // ---- Gate-thread constants (tid < 64): unit jj = tid>>1, batch gb = tid&1 ----
    const int gjj = tid >> 1;
    const int gb  = tid & 1;
    const int gjl = j0 + gjj;
    float bhr = 0.f, bhz = 0.f, bhn = 0.f;
    const float* xpp = xp;
    float* outp = out;
    if (tid < 64) {
        bhr = b_hh[gjl];
        bhz = b_hh[Hd + gjl];
        bhn = b_hh[2 * Hd + gjl];
        int bg = cid * 2 + gb;
        xpp  = xp  + (size_t)bg * Tt * G3 + gjl;
        outp = out + (size_t)bg * Tt * Hd + gjl;
    }

    for (int t = 0; t < Tt; t++) {
        const int cur = t & 1, nxt = cur ^ 1;
        const int last = (t == Tt - 1);

        // Prefetch xp for this step
        float xr = 0.f, xz = 0.f, xn = 0.f;
        if (tid < 64) {
            xr = __ldg(xpp);
            xz = __ldg(xpp + Hd);
            xn = __ldg(xpp + 2 * Hd);
        }

        // gh partials: w from registers, h broadcast from smem
        const float* h0 = &hs[cur][k0];
        const float* h1 = &hs[cur][Hd + k0];
        unsigned long long a0a = 0ull, a0b = 0ull, a1a = 0ull, a1b = 0ull;
#pragma unroll
        for (int i = 0; i < 32; i++) {
            ulonglong2 h0v = *(const ulonglong2*)(h0 + 4 * i);
            a0a = ffma2(wreg[2 * i],     h0v.x, a0a);
            a0b = ffma2(wreg[2 * i + 1], h0v.y, a0b);
            ulonglong2 h1v = *(const ulonglong2*)(h1 + 4 * i);
            a1a = ffma2(wreg[2 * i],     h1v.x, a1a);
            a1b = ffma2(wreg[2 * i + 1], h1v.y, a1b);
        }
        float2 p;
        p.x = (f2lo(a0a) + f2hi(a0a)) + (f2lo(a0b) + f2hi(a0b));
        p.y = (f2lo(a1a) + f2hi(a1a)) + (f2lo(a1b) + f2hi(a1b));
        *(float2*)&red[((g * 32 + lane) * 4 + ks) * 2] = p;
        __syncthreads();

        if (tid < 64) {
            const float* rr = &red[gb];
            int base = gjj * 8;
            float gr = (rr[base]       + rr[base + 2])       + (rr[base + 4]       + rr[base + 6]);
            float gz = (rr[256 + base] + rr[256 + base + 2]) + (rr[256 + base + 4] + rr[256 + base + 6]);
            float gn = (rr[512 + base] + rr[512 + base + 2]) + (rr[512 + base + 4] + rr[512 + base + 6]);
            float rg = sigmoidf_(xr + gr + bhr);
            float zg = sigmoidf_(xz + gz + bhz);
            float ng = tanhf(xn + rg * (gn + bhn));
            float hp = hs[cur][gb * Hd + gjl];
            float hnew = (1.0f - zg) * ng + zg * hp;

            *outp = do_gelu ? gelu_erf(hnew) : hnew;
            xpp += G3;
            outp += Hd;

            if (!last) {
                // Broadcast h_new to all 16 CTAs (plain weak cluster stores)
                uint32_t laddr = hs_base +
                    (uint32_t)((nxt * 2 * Hd + gb * Hd + gjl) * 4);
#pragma unroll
                for (int rd = 0; rd < CL; rd++) sts_cluster_f32(laddr, rd, hnew);

                // Order all 64 gate threads' stores, then one thread arrives
                asm volatile("bar.sync 1, 64;" ::: "memory");
                if (tid == 0) {
                    fence_cluster();
                    uint32_t lmb = mb_base + (uint32_t)(nxt * 8);
#pragma unroll
                    for (int rd = 0; rd < CL; rd++) mbar_arrive_remote(lmb, rd);
                }
            }
        }

        if (!last) {
            // Wait for all 16 CTAs' contributions to hs[nxt]
            mbar_wait_parity(mb_base + (uint32_t)(nxt * 8), (uint32_t)((t >> 1) & 1));
        }
    }
}

// ---------------------------------------------------------------------------
extern "C" void kernel_launch(void* const* d_in, const int* in_sizes, int n_in,
                              void* d_out, int out_size)
{
    const float* x     = (const float*)d_in[0];
    const float* w_ih1 = (const float*)d_in[1];
    const float* w_hh1 = (const float*)d_in[2];
    const float* b_ih1 = (const float*)d_in[3];
    const float* b_hh1 = (const float*)d_in[4];
    const float* w_ih2 = (const float*)d_in[5];
    const float* w_hh2 = (const float*)d_in[6];
    const float* b_ih2 = (const float*)d_in[7];
    const float* b_hh2 = (const float*)d_in[8];
    float* y = (float*)d_out;

    float *xp, *a;
    cudaGetSymbolAddress((void**)&xp, g_xp);
    cudaGetSymbolAddress((void**)&a,  g_a);

    cudaFuncSetAttribute(gru_scan_cl, cudaFuncAttributeNonPortableClusterSizeAllowed, 1);

    cudaLaunchConfig_t cfg = {};
    cfg.gridDim = dim3(NBLK, 1, 1);
    cfg.blockDim = dim3(SCAN_THREADS, 1, 1);
    cfg.dynamicSmemBytes = 0;
    cfg.stream = 0;
    cudaLaunchAttribute attrs[1];
    attrs[0].id = cudaLaunchAttributeClusterDimension;
    attrs[0].val.clusterDim.x = CL;
    attrs[0].val.clusterDim.y = 1;
    attrs[0].val.clusterDim.z = 1;
    cfg.attrs = attrs;
    cfg.numAttrs = 1;

    dim3 ggrid(G3 / 128, (Bz * Tt) / 128);   // 12 x 512

    // Layer 1
    gemm_nt_bias<<<ggrid, 256>>>(x, w_ih1, b_ih1, xp);
    cudaLaunchKernelEx(&cfg, gru_scan_cl, xp, w_hh1, b_hh1, a, 1);

    // Layer 2 (xp reused; scan1 fully consumed xp1 by stream order)
    gemm_nt_bias<<<ggrid, 256>>>(a, w_ih2, b_ih2, xp);
    cudaLaunchKernelEx(&cfg, gru_scan_cl, xp, w_hh2, b_hh2, y, 0);
}